// round 17
// baseline (speedup 1.0000x reference)
#include <cuda_runtime.h>
#include <cstdint>

// Problem constants
#define NCH      64          // input channels (= K per shift)
#define NOUT     64          // output channels
#define BAND_PX  200         // padded band length in pixels (198 used)
#define BAND_USED 198
#define BPAD     72          // padded N-stride of B slice in smem (conflict-free: 72%32=8)
#define PADW     34          // padded image width (32 + 2 reflect cols)
#define LASTPIX  1155

// smem layout (floats):
//  band[64*200] | S1[200] | S2[200] | Bs[64*72] | wpart[4*64] | wsum[64]
#define SMEM_FLOATS (NCH*BAND_PX + 2*BAND_PX + NCH*BPAD + 4*NOUT + NOUT)
#define SMEM_BYTES  (SMEM_FLOATS * 4)          // 72512 B -> 3 CTAs/SM

__device__ float g_Wr[576 * 64];   // tf32(rna)-rounded W, same [p][o] layout

__global__ void prep_round(const float* __restrict__ W) {
    int i = blockIdx.x * 256 + threadIdx.x;
    if (i < 576 * 64) {
        float r;
        asm("cvt.rna.tf32.f32 %0, %1;" : "=f"(r) : "f"(W[i]));
        g_Wr[i] = r;
    }
}

__device__ __forceinline__ float tf32r(float x) {
    float r;
    asm("cvt.rna.tf32.f32 %0, %1;" : "=f"(r) : "f"(x));
    return r;
}

__device__ __forceinline__ void mma8(float* d, const uint32_t* A, const uint32_t* B) {
    asm volatile(
        "mma.sync.aligned.m16n8k8.row.col.f32.tf32.tf32.f32 "
        "{%0,%1,%2,%3}, {%4,%5,%6,%7}, {%8,%9}, {%0,%1,%2,%3};\n"
        : "+f"(d[0]), "+f"(d[1]), "+f"(d[2]), "+f"(d[3])
        : "r"(A[0]), "r"(A[1]), "r"(A[2]), "r"(A[3]), "r"(B[0]), "r"(B[1]));
}

// register-free B fill: 64 rows (k=c) x 64 floats from g_Wr[(c*9+s)*64 ...]
__device__ __forceinline__ void fill_B(float* Bs, int s, int tid) {
    const int c   = tid & 63;
    const int ch0 = (tid >> 6) * 4;              // 4 chunk-groups of 4 x 16B
    const float* src = g_Wr + (c * 9 + s) * 64;
    uint32_t dst;
    {
        const float* p = Bs + c * BPAD;
        asm("{ .reg .u64 t; cvta.to.shared.u64 t, %1; cvt.u32.u64 %0, t; }"
            : "=r"(dst) : "l"(p));
    }
    #pragma unroll
    for (int i = 0; i < 4; ++i) {
        int ch = ch0 + i;                         // 16B chunk index 0..15 within row
        asm volatile("cp.async.cg.shared.global [%0], [%1], 16;\n"
                     :: "r"(dst + ch * 16), "l"(src + ch * 4));
    }
    asm volatile("cp.async.commit_group;\n");
}
#define CP_WAIT_ALL() asm volatile("cp.async.wait_group 0;\n" ::: "memory")

__global__ __launch_bounds__(256, 3)
void norm_conv_kernel(const float* __restrict__ a,
                      float* __restrict__ out)
{
    extern __shared__ float smem[];
    float* band  = smem;                      // 64*200
    float* S1    = band + NCH * BAND_PX;      // 200
    float* S2    = S1 + BAND_PX;              // 200
    float* Bs    = S2 + BAND_PX;              // 64*72 (single buffer)
    float* wpart = Bs + NCH * BPAD;           // 4*64
    float* wsum  = wpart + 4 * NOUT;          // 64

    const int tid    = threadIdx.x;
    const int b      = blockIdx.y;            // batch
    const int t      = blockIdx.x;            // pixel tile 0..8
    const int pstart = 128 * t;
    const int p0     = pstart + 35;

    const float* abase = a + (size_t)b * NCH * 1024;

    // ---- 0) kick off B slice for shift 0 (cp.async, overlaps band build) ----
    fill_B(Bs, 0, tid);

    // ---- 1) Load reflect-padded linear band into smem (tf32-rounded) ----
    for (int j = tid; j < NCH * BAND_PX; j += 256) {
        int c  = j / BAND_PX;
        int pp = j - c * BAND_PX;
        int pPad = min(pstart + pp, LASTPIX);
        int row = pPad / PADW;
        int col = pPad - row * PADW;
        int y = row - 1; y = (y < 0) ? 1 : ((y > 31) ? 30 : y);
        int x = col - 1; x = (x < 0) ? 1 : ((x > 31) ? 30 : x);
        band[c * BAND_PX + pp] = tf32r(abase[c * 1024 + y * 32 + x]);
    }

    // ---- 2) W column-sum partials from RAW W (via g_Wr? no — use raw-equal path) ----
    // NOTE: R5 used raw W here and passed; g_Wr is tf32-rounded. We preserve R5's
    // numerics by summing the SAME values the MMA consumes is not required (R5 proved
    // raw-W wsum passes at 2.9e-4); but we no longer have W as a parameter, so sum g_Wr.
    // Difference vs R5: wsum rounding ~1e-4 relative on a 4% term -> ~4e-6 effect.
    {
        int o = tid & 63;
        int q = tid >> 6;
        float s = 0.f;
        int pe = (q + 1) * 144;
        for (int p = q * 144; p < pe; ++p)
            s += g_Wr[p * 64 + o];
        wpart[q * 64 + o] = s;
    }
    __syncthreads();

    // ---- 3) Per-pixel channel sums S1/S2 + wsum reduce ----
    for (int pp = tid; pp < BAND_USED; pp += 256) {
        float s1 = 0.f, s2 = 0.f;
        #pragma unroll 8
        for (int c = 0; c < NCH; ++c) {
            float v = band[c * BAND_PX + pp];
            s1 += v;
            s2 += v * v;
        }
        S1[pp] = s1;
        S2[pp] = s2;
    }
    if (tid < 64)
        wsum[tid] = wpart[tid] + wpart[64 + tid] + wpart[128 + tid] + wpart[192 + tid];

    CP_WAIT_ALL();        // B slice 0 landed (per-thread) ...
    __syncthreads();      // ... and visible to all

    // ---- 4) Main MMA loop: 9 shifts x 8 k8-steps ----
    const int warp = tid >> 5;
    const int lane = tid & 31;
    const int gid  = lane >> 2;   // 0..7
    const int tig  = lane & 3;    // 0..3
    const int wm   = warp & 3;    // M-warp 0..3 (32 pixels each)
    const int wn   = warp >> 2;   // N-warp 0..1 (32 och each)

    float acc[2][4][4];
    #pragma unroll
    for (int mt = 0; mt < 2; ++mt)
        #pragma unroll
        for (int nt = 0; nt < 4; ++nt)
            #pragma unroll
            for (int r = 0; r < 4; ++r)
                acc[mt][nt][r] = 0.f;

    const uint32_t* bb = reinterpret_cast<const uint32_t*>(band);

    for (int s = 0; s < 9; ++s) {
        const uint32_t* bsu = reinterpret_cast<const uint32_t*>(Bs);
        int kh = s / 3;
        int kw = s - kh * 3;
        int delta = (kh - 1) * PADW + (kw - 1);
        int qa = 35 + wm * 32 + delta + gid;   // band pixel for A row 'gid'

        #pragma unroll
        for (int c0 = 0; c0 < NCH; c0 += 8) {
            uint32_t Af[2][4];
            int abase0 = (c0 + tig) * BAND_PX + qa;
            #pragma unroll
            for (int mt = 0; mt < 2; ++mt) {
                int ab = abase0 + mt * 16;
                Af[mt][0] = bb[ab];
                Af[mt][1] = bb[ab + 8];
                Af[mt][2] = bb[ab + 4 * BAND_PX];
                Af[mt][3] = bb[ab + 4 * BAND_PX + 8];
            }
            int bbase = (c0 + tig) * BPAD + wn * 32 + gid;
            #pragma unroll
            for (int nt = 0; nt < 4; ++nt) {
                uint32_t Bf[2];
                Bf[0] = bsu[bbase + nt * 8];
                Bf[1] = bsu[bbase + nt * 8 + 4 * BPAD];
                #pragma unroll
                for (int mt = 0; mt < 2; ++mt)
                    mma8(acc[mt][nt], Af[mt], Bf);
            }
        }

        if (s < 8) {
            __syncthreads();           // all warps done reading Bs
            fill_B(Bs, s + 1, tid);    // register-free refill
            CP_WAIT_ALL();
            __syncthreads();
        }
    }

    // ---- 5) Epilogue: out = (raw - mean * wsum[o]) / std ----
    #pragma unroll
    for (int mt = 0; mt < 2; ++mt) {
        #pragma unroll
        for (int half = 0; half < 2; ++half) {
            int q = 35 + wm * 32 + mt * 16 + gid + half * 8;
            float psum = 0.f, psq = 0.f;
            #pragma unroll
            for (int dr = -1; dr <= 1; ++dr)
                #pragma unroll
                for (int dc = -1; dc <= 1; ++dc) {
                    int qq = q + dr * PADW + dc;
                    psum += S1[qq];
                    psq  += S2[qq];
                }
            float mean = psum * (1.0f / 576.0f);
            float var  = (psq - psum * psum * (1.0f / 576.0f)) * (1.0f / 575.0f);
            float rstd = rsqrtf(var);

            int p   = p0 + wm * 32 + mt * 16 + gid + half * 8;
            int row = p / PADW;
            int col = p - row * PADW;
            bool valid = (col >= 1) && (col <= 32) && (row >= 1) && (row <= 32);
            if (valid) {
                int y = row - 1, x = col - 1;
                float* obase = out + (size_t)b * NOUT * 1024 + y * 32 + x;
                #pragma unroll
                for (int nt = 0; nt < 4; ++nt) {
                    int o = wn * 32 + nt * 8 + tig * 2;
                    float v0 = (acc[mt][nt][half * 2 + 0] - mean * wsum[o])     * rstd;
                    float v1 = (acc[mt][nt][half * 2 + 1] - mean * wsum[o + 1]) * rstd;
                    obase[(size_t)o * 1024]       = v0;
                    obase[(size_t)(o + 1) * 1024] = v1;
                }
            }
        }
    }
}

extern "C" void kernel_launch(void* const* d_in, const int* in_sizes, int n_in,
                              void* d_out, int out_size)
{
    const float* a = (const float*)d_in[0];     // [256,64,32,32]
    const float* W = (const float*)d_in[1];     // [576,64]
    float* out = (float*)d_out;                 // [256,64,32,32]

    cudaFuncSetAttribute(norm_conv_kernel,
                         cudaFuncAttributeMaxDynamicSharedMemorySize, SMEM_BYTES);

    prep_round<<<144, 256>>>(W);

    dim3 grid(9, 256);   // 9 pixel tiles x 256 batches
    norm_conv_kernel<<<grid, 256, SMEM_BYTES>>>(a, out);
}